// round 11
// baseline (speedup 1.0000x reference)
#include <cuda_runtime.h>
#include <math.h>
#include <math_constants.h>

#define SS 2048
#define BB 64
#define HH 1024
#define CH 128
#define CHUNKS (SS/CH)          // 16
#define NBLK1 (BB*CHUNKS)       // 1024
#define REC 1040                // 1024 acc + m + z (padded)
#define NSP1 24                 // fc1 partials: 16 attn-half + 8 key-half
#define NSP2 16                 // fc2 partials

// ---------------- scratch (no allocations allowed) ----------------
__device__ float g_part[NBLK1 * REC];        // ~4.3 MB partial softmax records
__device__ float g_attn[BB * HH];            // attention-pooled context
__device__ float g_x1[BB * HH];              // fc1 output (post bias)
__device__ float g_x1p[NSP1 * BB * HH];      // gemm1 k-split partials (6 MB)
__device__ float g_x2[BB * HH];              // bn+tanh output
__device__ float g_x3p[NSP2 * BB * HH];      // gemm2 k-split partials (4 MB)

// ---------------- K1: fused scores + online-softmax weighted sum ----------------
__global__ __launch_bounds__(256, 2) void k_attn_partial(
    const float* __restrict__ ctx, const float* __restrict__ key,
    const float* __restrict__ mask, float* __restrict__ scores_raw)
{
    int blk = blockIdx.x;
    int b = blk / CHUNKS;
    int chunk = blk % CHUNKS;
    int s0 = chunk * CH;
    int tid = threadIdx.x;
    int w = tid >> 5;
    int lane = tid & 31;

    const float4* keyv = (const float4*)(key + (size_t)b * HH);
    float4 k4[8];
#pragma unroll
    for (int j = 0; j < 8; j++) k4[j] = keyv[j * 32 + lane];

    float4 a4[8];
#pragma unroll
    for (int j = 0; j < 8; j++) a4[j] = make_float4(0.f, 0.f, 0.f, 0.f);
    float m = -3.0e38f, z = 0.f;

    for (int t = 0; t < CH / 8; t++) {
        int s = s0 + w + t * 8;
        const float4* row = (const float4*)(ctx + ((size_t)s * BB + b) * HH);
        float4 r4[8];
#pragma unroll
        for (int j = 0; j < 8; j++) r4[j] = row[j * 32 + lane];

        float p = 0.f;
#pragma unroll
        for (int j = 0; j < 8; j++)
            p += r4[j].x * k4[j].x + r4[j].y * k4[j].y + r4[j].z * k4[j].z + r4[j].w * k4[j].w;
#pragma unroll
        for (int off = 16; off > 0; off >>= 1)
            p += __shfl_xor_sync(0xffffffffu, p, off);

        float score = p + mask[(size_t)b * SS + s];
        if (lane == 0) scores_raw[(size_t)b * SS + s] = score;

        float mn = fmaxf(m, score);
        float alpha = __expf(m - mn);
        float pe = __expf(score - mn);
        z = z * alpha + pe;
#pragma unroll
        for (int j = 0; j < 8; j++) {
            a4[j].x = a4[j].x * alpha + pe * r4[j].x;
            a4[j].y = a4[j].y * alpha + pe * r4[j].y;
            a4[j].z = a4[j].z * alpha + pe * r4[j].z;
            a4[j].w = a4[j].w * alpha + pe * r4[j].w;
        }
        m = mn;
    }

    __shared__ float sm[8], sz[8];
    __shared__ float sacc8[8][HH];       // 32 KB
    if (lane == 0) { sm[w] = m; sz[w] = z; }
    __syncthreads();
    float mc = sm[0];
#pragma unroll
    for (int i = 1; i < 8; i++) mc = fmaxf(mc, sm[i]);
    float scale = __expf(m - mc);

    float4* myrow = (float4*)sacc8[w];
#pragma unroll
    for (int j = 0; j < 8; j++) {
        float4 v;
        v.x = a4[j].x * scale; v.y = a4[j].y * scale;
        v.z = a4[j].z * scale; v.w = a4[j].w * scale;
        myrow[j * 32 + lane] = v;
    }
    __syncthreads();

    float zc = 0.f;
#pragma unroll
    for (int i = 0; i < 8; i++) zc += sz[i] * __expf(sm[i] - mc);

    float* rec = g_part + (size_t)blk * REC;
    {
        float4 acc = *(float4*)&sacc8[0][tid * 4];
#pragma unroll
        for (int i = 1; i < 8; i++) {
            float4 v = *(float4*)&sacc8[i][tid * 4];
            acc.x += v.x; acc.y += v.y; acc.z += v.z; acc.w += v.w;
        }
        *(float4*)(rec + tid * 4) = acc;
    }
    if (tid == 0) { rec[HH] = mc; rec[HH + 1] = zc; }
}

// ---------------- shared GEMM body: 64b x 128i tile, 4x8 acc ----------------
template<bool SYNC>
__device__ __forceinline__ void gemm_body(
    const float* __restrict__ A, const float* __restrict__ W,
    int wstride, int kchunk, int i0, int k0A, int k0W,
    float* __restrict__ op, float (&As)[16][68], float (&Ws)[16][132], int tid)
{
    int tb = tid & 15, ti = tid >> 4;
    int rowA = tid >> 2;            // 0..63
    int kqA  = (tid & 3) * 4;       // 0,4,8,12
    int rowW = tid >> 1;            // 0..127
    int kqW  = (tid & 1) * 8;       // 0,8
    int niter = kchunk >> 4;

    // independent prologue: weight prefetch (inputs, never produced upstream)
    float4 pw0, pw1;
    const float* wp0 = W + (size_t)(i0 + rowW) * wstride + k0W + kqW;
    pw0 = *(const float4*)wp0;
    pw1 = *(const float4*)(wp0 + 4);

    if (SYNC) cudaGridDependencySynchronize();

    float4 pa = *(const float4*)(A + (size_t)rowA * HH + k0A + kqA);

    float acc[4][8];
#pragma unroll
    for (int a = 0; a < 4; a++)
#pragma unroll
        for (int c = 0; c < 8; c++) acc[a][c] = 0.f;

    for (int kk = 0; kk < niter; kk++) {
        As[kqA + 0][rowA] = pa.x; As[kqA + 1][rowA] = pa.y;
        As[kqA + 2][rowA] = pa.z; As[kqA + 3][rowA] = pa.w;
        Ws[kqW + 0][rowW] = pw0.x; Ws[kqW + 1][rowW] = pw0.y;
        Ws[kqW + 2][rowW] = pw0.z; Ws[kqW + 3][rowW] = pw0.w;
        Ws[kqW + 4][rowW] = pw1.x; Ws[kqW + 5][rowW] = pw1.y;
        Ws[kqW + 6][rowW] = pw1.z; Ws[kqW + 7][rowW] = pw1.w;
        __syncthreads();

        if (kk + 1 < niter) {
            int kof = (kk + 1) * 16;
            pa = *(const float4*)(A + (size_t)rowA * HH + k0A + kof + kqA);
            const float* wp = W + (size_t)(i0 + rowW) * wstride + k0W + kof + kqW;
            pw0 = *(const float4*)wp;
            pw1 = *(const float4*)(wp + 4);
        }

#pragma unroll
        for (int kt = 0; kt < 16; kt++) {
            float4 av  = *(const float4*)&As[kt][tb * 4];
            float4 wv0 = *(const float4*)&Ws[kt][ti * 8];
            float4 wv1 = *(const float4*)&Ws[kt][ti * 8 + 4];
            float a0 = av.x, a1 = av.y, a2 = av.z, a3 = av.w;
            acc[0][0] += a0 * wv0.x; acc[0][1] += a0 * wv0.y; acc[0][2] += a0 * wv0.z; acc[0][3] += a0 * wv0.w;
            acc[0][4] += a0 * wv1.x; acc[0][5] += a0 * wv1.y; acc[0][6] += a0 * wv1.z; acc[0][7] += a0 * wv1.w;
            acc[1][0] += a1 * wv0.x; acc[1][1] += a1 * wv0.y; acc[1][2] += a1 * wv0.z; acc[1][3] += a1 * wv0.w;
            acc[1][4] += a1 * wv1.x; acc[1][5] += a1 * wv1.y; acc[1][6] += a1 * wv1.z; acc[1][7] += a1 * wv1.w;
            acc[2][0] += a2 * wv0.x; acc[2][1] += a2 * wv0.y; acc[2][2] += a2 * wv0.z; acc[2][3] += a2 * wv0.w;
            acc[2][4] += a2 * wv1.x; acc[2][5] += a2 * wv1.y; acc[2][6] += a2 * wv1.z; acc[2][7] += a2 * wv1.w;
            acc[3][0] += a3 * wv0.x; acc[3][1] += a3 * wv0.y; acc[3][2] += a3 * wv0.z; acc[3][3] += a3 * wv0.w;
            acc[3][4] += a3 * wv1.x; acc[3][5] += a3 * wv1.y; acc[3][6] += a3 * wv1.z; acc[3][7] += a3 * wv1.w;
        }
        __syncthreads();
    }

#pragma unroll
    for (int cb = 0; cb < 4; cb++) {
        int b = tb * 4 + cb;
        float* dst = op + (size_t)b * HH + i0 + ti * 8;
        *(float4*)dst = make_float4(acc[cb][0], acc[cb][1], acc[cb][2], acc[cb][3]);
        *(float4*)(dst + 4) = make_float4(acc[cb][4], acc[cb][5], acc[cb][6], acc[cb][7]);
    }
}

// ---------------- K2: combine + At normalize (320 CTAs, sync) + key-half fc1 GEMM (64 CTAs, NO sync) ----------------
// grid = 384: bid<320 -> combine (b = bid&63, part = bid>>6); bid>=320 -> keygemm (runs under K1!)
__global__ __launch_bounds__(256) void k_combine_kg(
    float* __restrict__ at, const float* __restrict__ key,
    const float* __restrict__ fc1w)
{
    __shared__ float As[16][68];
    __shared__ float Ws[16][132];
    int bid = blockIdx.x;
    int tid = threadIdx.x;

    if (bid >= 320) {
        // key-half of fc1: A = key, W cols [1024,2048). Independent of K1 -> no sync.
        int g = bid - 320;          // 0..63
        int ks = g & 7;             // ksplit 0..7, kchunk=128
        int it = g >> 3;            // i-tile 0..7
        gemm_body<false>(key, fc1w, 2 * HH, 128, it * 128, ks * 128, HH + ks * 128,
                         g_x1p + (size_t)(16 + ks) * BB * HH, As, Ws, tid);
        return;
    }

    cudaGridDependencySynchronize();   // combine needs K1 output

    int b = bid & 63;
    int part = bid >> 6;

    float mb = -3.0e38f;
#pragma unroll
    for (int c = 0; c < CHUNKS; c++)
        mb = fmaxf(mb, g_part[(size_t)(b * CHUNKS + c) * REC + HH]);
    float zb = 0.f;
#pragma unroll
    for (int c = 0; c < CHUNKS; c++) {
        const float* rec = g_part + (size_t)(b * CHUNKS + c) * REC;
        zb += rec[HH + 1] * __expf(rec[HH] - mb);
    }
    float inv = 1.f / zb;

    if (part < 4) {
        float cs[CHUNKS];
#pragma unroll
        for (int c = 0; c < CHUNKS; c++)
            cs[c] = __expf(g_part[(size_t)(b * CHUNKS + c) * REC + HH] - mb);
        int h = part * 256 + tid;
        float acc = 0.f;
#pragma unroll
        for (int c = 0; c < CHUNKS; c++)
            acc += g_part[(size_t)(b * CHUNKS + c) * REC + h] * cs[c];
        g_attn[(size_t)b * HH + h] = acc * inv;
    } else {
        float4* atv = (float4*)(at + (size_t)b * SS);
        for (int s = tid; s < SS / 4; s += 256) {
            float4 v = atv[s];
            v.x = __expf(v.x - mb) * inv;
            v.y = __expf(v.y - mb) * inv;
            v.z = __expf(v.z - mb) * inv;
            v.w = __expf(v.w - mb) * inv;
            atv[s] = v;
        }
    }
}

// ---------------- standalone GEMM (attn-half fc1 / fc2): grid (8, 16), kchunk=64 ----------------
__global__ __launch_bounds__(256) void k_gemm(
    const float* __restrict__ A, const float* __restrict__ W,
    int wstride, float* __restrict__ outp)
{
    __shared__ float As[16][68];
    __shared__ float Ws[16][132];
    int k0 = blockIdx.y * 64;
    gemm_body<true>(A, W, wstride, 64, blockIdx.x * 128, k0, k0,
                    outp + (size_t)blockIdx.y * BB * HH, As, Ws, threadIdx.x);
}

// ---------------- reduce k-split partials + bias ----------------
// NPL partials per lane (4 lanes per output float4).
template<int NPL>
__global__ void k_red(const float* __restrict__ bias, const float* __restrict__ parts,
                      float* __restrict__ out)
{
    int t = blockIdx.x * 256 + threadIdx.x;   // 0..65535
    int o = t >> 2;                            // float4 slot 0..16383
    int pg = t & 3;

    float4 bv = make_float4(0.f, 0.f, 0.f, 0.f);
    if (pg == 0) {
        int i4 = (o * 4) & (HH - 1);
        bv = *(const float4*)(bias + i4);
    }

    cudaGridDependencySynchronize();

    float4 v = make_float4(0.f, 0.f, 0.f, 0.f);
#pragma unroll
    for (int p = 0; p < NPL; p++) {
        float4 x = *(const float4*)(parts + (size_t)(pg * NPL + p) * BB * HH + (size_t)o * 4);
        v.x += x.x; v.y += x.y; v.z += x.z; v.w += x.w;
    }
#pragma unroll
    for (int off = 1; off <= 2; off <<= 1) {
        v.x += __shfl_xor_sync(0xffffffffu, v.x, off);
        v.y += __shfl_xor_sync(0xffffffffu, v.y, off);
        v.z += __shfl_xor_sync(0xffffffffu, v.z, off);
        v.w += __shfl_xor_sync(0xffffffffu, v.w, off);
    }
    if (pg == 0) {
        v.x += bv.x; v.y += bv.y; v.z += bv.z; v.w += bv.w;
        *(float4*)(out + (size_t)o * 4) = v;
    }
}

// ---------------- BatchNorm (training stats, biased var) + tanh ----------------
__global__ void k_bn(const float* __restrict__ gamma, const float* __restrict__ beta)
{
    int i0 = blockIdx.x * 64;
    int tid = threadIdx.x;
    int ic = tid & 63;
    int rg = tid >> 6;            // 0..3
    int i = i0 + ic;

    float g = gamma[i], be = beta[i];
    cudaGridDependencySynchronize();

    float v[16];
#pragma unroll
    for (int j = 0; j < 16; j++)
        v[j] = g_x1[(size_t)(rg * 16 + j) * HH + i];

    __shared__ float red[4][64];
    float s1 = 0.f;
#pragma unroll
    for (int j = 0; j < 16; j++) s1 += v[j];
    red[rg][ic] = s1;
    __syncthreads();
    float mean = (red[0][ic] + red[1][ic] + red[2][ic] + red[3][ic]) * (1.f / 64.f);
    __syncthreads();

    float s2 = 0.f;
#pragma unroll
    for (int j = 0; j < 16; j++) { float d = v[j] - mean; s2 += d * d; }
    red[rg][ic] = s2;
    __syncthreads();
    float var = (red[0][ic] + red[1][ic] + red[2][ic] + red[3][ic]) * (1.f / 64.f);
    float rstd = rsqrtf(var + 1e-5f);

#pragma unroll
    for (int j = 0; j < 16; j++) {
        float x = (v[j] - mean) * rstd * g + be;
        g_x2[(size_t)(rg * 16 + j) * HH + i] = tanhf(x);
    }
}

// ---------------- PDL launch helper ----------------
static void launch_pdl(const void* func, dim3 grid, dim3 block, void** args)
{
    cudaLaunchConfig_t cfg = {};
    cfg.gridDim = grid;
    cfg.blockDim = block;
    cfg.dynamicSmemBytes = 0;
    cfg.stream = 0;
    cudaLaunchAttribute attr[1];
    attr[0].id = cudaLaunchAttributeProgrammaticStreamSerialization;
    attr[0].val.programmaticStreamSerializationAllowed = 1;
    cfg.attrs = attr;
    cfg.numAttrs = 1;
    cudaLaunchKernelExC(&cfg, func, args);
}

// ---------------- launch ----------------
extern "C" void kernel_launch(void* const* d_in, const int* in_sizes, int n_in,
                              void* d_out, int out_size)
{
    const float* ctx   = (const float*)d_in[0];
    const float* key   = (const float*)d_in[1];
    const float* mask  = (const float*)d_in[2];
    const float* fc1_w = (const float*)d_in[3];
    const float* fc1_b = (const float*)d_in[4];
    const float* bn_g  = (const float*)d_in[5];
    const float* bn_b  = (const float*)d_in[6];
    const float* fc2_w = (const float*)d_in[7];
    const float* fc2_b = (const float*)d_in[8];

    float* out_x  = (float*)d_out;                 // (B, H)
    float* out_at = (float*)d_out + BB * HH;       // (B, S)

    float *p_x1p, *p_x1, *p_x3p, *p_attn, *p_x2;
    cudaGetSymbolAddress((void**)&p_x1p, g_x1p);
    cudaGetSymbolAddress((void**)&p_x1,  g_x1);
    cudaGetSymbolAddress((void**)&p_x3p, g_x3p);
    cudaGetSymbolAddress((void**)&p_attn, g_attn);
    cudaGetSymbolAddress((void**)&p_x2,  g_x2);

    // 1) fused scores + online softmax weighted sum (single pass over ctx)
    k_attn_partial<<<NBLK1, 256>>>(ctx, key, mask, out_at);

    // 2) combine + At normalize (sync CTAs) + key-half fc1 GEMM (free CTAs under K1)
    {
        void* args[] = { &out_at, (void*)&key, (void*)&fc1_w };
        launch_pdl((const void*)k_combine_kg, dim3(384), dim3(256), args);
    }
    // 3) fc1 attn-half: g_attn @ fc1_w[:, :1024]^T  (ksplit 16, kchunk 64)
    {
        int ws = 2 * HH;
        void* args[] = { &p_attn, (void*)&fc1_w, &ws, &p_x1p };
        launch_pdl((const void*)k_gemm, dim3(8, 16), dim3(256), args);
    }
    // 4) reduce 24 partials + bias
    {
        void* args[] = { (void*)&fc1_b, &p_x1p, &p_x1 };
        launch_pdl((const void*)k_red<6>, dim3(256), dim3(256), args);
    }
    // 5) batchnorm + tanh
    {
        void* args[] = { (void*)&bn_g, (void*)&bn_b };
        launch_pdl((const void*)k_bn, dim3(HH / 64), dim3(256), args);
    }
    // 6) fc2 (ksplit 16, kchunk 64)
    {
        int ws = HH;
        void* args[] = { &p_x2, (void*)&fc2_w, &ws, &p_x3p };
        launch_pdl((const void*)k_gemm, dim3(8, 16), dim3(256), args);
    }
    // 7) reduce 16 partials + bias -> out
    {
        void* args[] = { (void*)&fc2_b, &p_x3p, &out_x };
        launch_pdl((const void*)k_red<4>, dim3(256), dim3(256), args);
    }
}

// round 16
// speedup vs baseline: 1.0479x; 1.0479x over previous
#include <cuda_runtime.h>
#include <math.h>
#include <math_constants.h>

#define SS 2048
#define BB 64
#define HH 1024
#define CH 128
#define CHUNKS (SS/CH)          // 16
#define NBLK1 (BB*CHUNKS)       // 1024
#define REC 1040                // 1024 acc + m + z (padded)
#define NSPLIT 16

// ---------------- scratch (no allocations allowed) ----------------
__device__ float g_part[NBLK1 * REC];        // ~4.3 MB partial softmax records
__device__ float g_attn[BB * HH];            // attention-pooled context
__device__ float g_x1p[NSPLIT * BB * HH];    // gemm1 k-split partials (4 MB)
__device__ float g_x2[BB * HH];              // bn+tanh output
__device__ float g_x3p[NSPLIT * BB * HH];    // gemm2 k-split partials (4 MB)

// ---------------- K1: fused scores + online-softmax weighted sum ----------------
__global__ __launch_bounds__(256, 2) void k_attn_partial(
    const float* __restrict__ ctx, const float* __restrict__ key,
    const float* __restrict__ mask, float* __restrict__ scores_raw)
{
    int blk = blockIdx.x;
    int b = blk / CHUNKS;
    int chunk = blk % CHUNKS;
    int s0 = chunk * CH;
    int tid = threadIdx.x;
    int w = tid >> 5;
    int lane = tid & 31;

    const float4* keyv = (const float4*)(key + (size_t)b * HH);
    float4 k4[8];
#pragma unroll
    for (int j = 0; j < 8; j++) k4[j] = keyv[j * 32 + lane];

    float4 a4[8];
#pragma unroll
    for (int j = 0; j < 8; j++) a4[j] = make_float4(0.f, 0.f, 0.f, 0.f);
    float m = -3.0e38f, z = 0.f;

    for (int t = 0; t < CH / 8; t++) {
        int s = s0 + w + t * 8;
        const float4* row = (const float4*)(ctx + ((size_t)s * BB + b) * HH);
        float4 r4[8];
#pragma unroll
        for (int j = 0; j < 8; j++) r4[j] = row[j * 32 + lane];

        float p = 0.f;
#pragma unroll
        for (int j = 0; j < 8; j++)
            p += r4[j].x * k4[j].x + r4[j].y * k4[j].y + r4[j].z * k4[j].z + r4[j].w * k4[j].w;
#pragma unroll
        for (int off = 16; off > 0; off >>= 1)
            p += __shfl_xor_sync(0xffffffffu, p, off);

        float score = p + mask[(size_t)b * SS + s];
        if (lane == 0) scores_raw[(size_t)b * SS + s] = score;

        float mn = fmaxf(m, score);
        float alpha = __expf(m - mn);
        float pe = __expf(score - mn);
        z = z * alpha + pe;
#pragma unroll
        for (int j = 0; j < 8; j++) {
            a4[j].x = a4[j].x * alpha + pe * r4[j].x;
            a4[j].y = a4[j].y * alpha + pe * r4[j].y;
            a4[j].z = a4[j].z * alpha + pe * r4[j].z;
            a4[j].w = a4[j].w * alpha + pe * r4[j].w;
        }
        m = mn;
    }

    __shared__ float sm[8], sz[8];
    __shared__ float sacc8[8][HH];       // 32 KB
    if (lane == 0) { sm[w] = m; sz[w] = z; }
    __syncthreads();
    float mc = sm[0];
#pragma unroll
    for (int i = 1; i < 8; i++) mc = fmaxf(mc, sm[i]);
    float scale = __expf(m - mc);

    float4* myrow = (float4*)sacc8[w];
#pragma unroll
    for (int j = 0; j < 8; j++) {
        float4 v;
        v.x = a4[j].x * scale; v.y = a4[j].y * scale;
        v.z = a4[j].z * scale; v.w = a4[j].w * scale;
        myrow[j * 32 + lane] = v;
    }
    __syncthreads();

    float zc = 0.f;
#pragma unroll
    for (int i = 0; i < 8; i++) zc += sz[i] * __expf(sm[i] - mc);

    float* rec = g_part + (size_t)blk * REC;
    {
        float4 acc = *(float4*)&sacc8[0][tid * 4];
#pragma unroll
        for (int i = 1; i < 8; i++) {
            float4 v = *(float4*)&sacc8[i][tid * 4];
            acc.x += v.x; acc.y += v.y; acc.z += v.z; acc.w += v.w;
        }
        *(float4*)(rec + tid * 4) = acc;
    }
    if (tid == 0) { rec[HH] = mc; rec[HH + 1] = zc; }
}

// ---------------- K2: merge chunk partials per b + normalize At (parallel) ----------------
__global__ void k_combine(float* __restrict__ at)
{
    int part = blockIdx.x;
    int b = blockIdx.y;
    int tid = threadIdx.x;

    cudaGridDependencySynchronize();   // wait for K1 partials

    float mb = -3.0e38f;
#pragma unroll
    for (int c = 0; c < CHUNKS; c++)
        mb = fmaxf(mb, g_part[(size_t)(b * CHUNKS + c) * REC + HH]);
    float zb = 0.f;
#pragma unroll
    for (int c = 0; c < CHUNKS; c++) {
        const float* rec = g_part + (size_t)(b * CHUNKS + c) * REC;
        zb += rec[HH + 1] * __expf(rec[HH] - mb);
    }
    float inv = 1.f / zb;

    if (part < 4) {
        float cs[CHUNKS];
#pragma unroll
        for (int c = 0; c < CHUNKS; c++)
            cs[c] = __expf(g_part[(size_t)(b * CHUNKS + c) * REC + HH] - mb);
        int h = part * 256 + tid;
        float acc = 0.f;
#pragma unroll
        for (int c = 0; c < CHUNKS; c++)
            acc += g_part[(size_t)(b * CHUNKS + c) * REC + h] * cs[c];
        g_attn[(size_t)b * HH + h] = acc * inv;
    } else {
        float4* atv = (float4*)(at + (size_t)b * SS);
        for (int s = tid; s < SS / 4; s += 256) {
            float4 v = atv[s];
            v.x = __expf(v.x - mb) * inv;
            v.y = __expf(v.y - mb) * inv;
            v.z = __expf(v.z - mb) * inv;
            v.w = __expf(v.w - mb) * inv;
            atv[s] = v;
        }
    }
}

// ---------------- GEMM: 64b x 128i tile, 4x8 acc/thread, register-prefetch ----------------
// grid = (8 i-tiles, 16 ksplit), block = 256. W prefetch overlaps predecessor via PDL.
__global__ __launch_bounds__(256) void k_gemm(
    const float* __restrict__ A1, const float* __restrict__ A2,
    const float* __restrict__ W, int wstride, int kchunk, float* __restrict__ outp)
{
    __shared__ float As[16][68];
    __shared__ float Ws[16][132];
    int i0 = blockIdx.x * 128;
    int k0 = blockIdx.y * kchunk;
    int tid = threadIdx.x;
    int tb = tid & 15, ti = tid >> 4;
    int rowA = tid >> 2;            // 0..63
    int kqA  = (tid & 3) * 4;       // 0,4,8,12
    int rowW = tid >> 1;            // 0..127
    int kqW  = (tid & 1) * 8;       // 0,8
    int niter = kchunk >> 4;

    // independent prologue: weight tile prefetch (inputs, not producer output)
    float4 pa, pw0, pw1;
    {
        const float* wp = W + (size_t)(i0 + rowW) * wstride + k0 + kqW;
        pw0 = *(const float4*)wp;
        pw1 = *(const float4*)(wp + 4);
    }

    cudaGridDependencySynchronize();   // A (g_attn / g_x2) ready after this

    {
        int k = k0 + kqA;
        const float* ap = (k < HH) ? (A1 + (size_t)rowA * HH + k)
                                   : (A2 + (size_t)rowA * HH + (k - HH));
        pa = *(const float4*)ap;
    }

    float acc[4][8];
#pragma unroll
    for (int a = 0; a < 4; a++)
#pragma unroll
        for (int c = 0; c < 8; c++) acc[a][c] = 0.f;

    for (int kk = 0; kk < niter; kk++) {
        As[kqA + 0][rowA] = pa.x; As[kqA + 1][rowA] = pa.y;
        As[kqA + 2][rowA] = pa.z; As[kqA + 3][rowA] = pa.w;
        Ws[kqW + 0][rowW] = pw0.x; Ws[kqW + 1][rowW] = pw0.y;
        Ws[kqW + 2][rowW] = pw0.z; Ws[kqW + 3][rowW] = pw0.w;
        Ws[kqW + 4][rowW] = pw1.x; Ws[kqW + 5][rowW] = pw1.y;
        Ws[kqW + 6][rowW] = pw1.z; Ws[kqW + 7][rowW] = pw1.w;
        __syncthreads();

        if (kk + 1 < niter) {
            int k = k0 + (kk + 1) * 16;
            int ka = k + kqA;
            const float* ap = (ka < HH) ? (A1 + (size_t)rowA * HH + ka)
                                        : (A2 + (size_t)rowA * HH + (ka - HH));
            pa = *(const float4*)ap;
            const float* wp = W + (size_t)(i0 + rowW) * wstride + k + kqW;
            pw0 = *(const float4*)wp;
            pw1 = *(const float4*)(wp + 4);
        }

#pragma unroll
        for (int kt = 0; kt < 16; kt++) {
            float4 av  = *(const float4*)&As[kt][tb * 4];
            float4 wv0 = *(const float4*)&Ws[kt][ti * 8];
            float4 wv1 = *(const float4*)&Ws[kt][ti * 8 + 4];
            float a0 = av.x, a1 = av.y, a2 = av.z, a3 = av.w;
            acc[0][0] += a0 * wv0.x; acc[0][1] += a0 * wv0.y; acc[0][2] += a0 * wv0.z; acc[0][3] += a0 * wv0.w;
            acc[0][4] += a0 * wv1.x; acc[0][5] += a0 * wv1.y; acc[0][6] += a0 * wv1.z; acc[0][7] += a0 * wv1.w;
            acc[1][0] += a1 * wv0.x; acc[1][1] += a1 * wv0.y; acc[1][2] += a1 * wv0.z; acc[1][3] += a1 * wv0.w;
            acc[1][4] += a1 * wv1.x; acc[1][5] += a1 * wv1.y; acc[1][6] += a1 * wv1.z; acc[1][7] += a1 * wv1.w;
            acc[2][0] += a2 * wv0.x; acc[2][1] += a2 * wv0.y; acc[2][2] += a2 * wv0.z; acc[2][3] += a2 * wv0.w;
            acc[2][4] += a2 * wv1.x; acc[2][5] += a2 * wv1.y; acc[2][6] += a2 * wv1.z; acc[2][7] += a2 * wv1.w;
            acc[3][0] += a3 * wv0.x; acc[3][1] += a3 * wv0.y; acc[3][2] += a3 * wv0.z; acc[3][3] += a3 * wv0.w;
            acc[3][4] += a3 * wv1.x; acc[3][5] += a3 * wv1.y; acc[3][6] += a3 * wv1.z; acc[3][7] += a3 * wv1.w;
        }
        __syncthreads();
    }

    float* op = outp + (size_t)blockIdx.y * BB * HH;
#pragma unroll
    for (int cb = 0; cb < 4; cb++) {
        int b = tb * 4 + cb;
        float* dst = op + (size_t)b * HH + i0 + ti * 8;
        *(float4*)dst = make_float4(acc[cb][0], acc[cb][1], acc[cb][2], acc[cb][3]);
        *(float4*)(dst + 4) = make_float4(acc[cb][4], acc[cb][5], acc[cb][6], acc[cb][7]);
    }
}

// ---------------- fused: reduce 16 fc1 partials + bias + BatchNorm + tanh -> g_x2 ----------------
// grid = 128 (8 features each), block = 256. Thread: feature fi, 2 batch rows.
__global__ __launch_bounds__(256) void k_red_bn(
    const float* __restrict__ bias, const float* __restrict__ gamma,
    const float* __restrict__ beta)
{
    int bid = blockIdx.x;
    int tid = threadIdx.x;
    int fi = tid & 7;              // feature within CTA
    int rg = tid >> 3;             // 0..31, two batch rows each
    int f = bid * 8 + fi;

    // independent prologue: per-feature params
    float bi = bias[f], gam = gamma[f], bet = beta[f];

    cudaGridDependencySynchronize();   // gemm1 partials ready

    int b0 = rg * 2, b1 = b0 + 1;
    float v0 = bi, v1 = bi;
#pragma unroll
    for (int p = 0; p < NSPLIT; p++) {
        const float* pp = g_x1p + (size_t)p * BB * HH + f;
        v0 += pp[(size_t)b0 * HH];
        v1 += pp[(size_t)b1 * HH];
    }

    __shared__ float sred[32][9];
    sred[rg][fi] = v0 + v1;
    __syncthreads();
#pragma unroll
    for (int st = 16; st >= 1; st >>= 1) {
        if (rg < st) sred[rg][fi] += sred[rg + st][fi];
        __syncthreads();
    }
    float mean = sred[0][fi] * (1.f / 64.f);
    __syncthreads();

    float d0 = v0 - mean, d1 = v1 - mean;
    sred[rg][fi] = d0 * d0 + d1 * d1;
    __syncthreads();
#pragma unroll
    for (int st = 16; st >= 1; st >>= 1) {
        if (rg < st) sred[rg][fi] += sred[rg + st][fi];
        __syncthreads();
    }
    float rstd = rsqrtf(sred[0][fi] * (1.f / 64.f) + 1e-5f);

    g_x2[(size_t)b0 * HH + f] = tanhf(d0 * rstd * gam + bet);
    g_x2[(size_t)b1 * HH + f] = tanhf(d1 * rstd * gam + bet);
}

// ---------------- reduce fc2 partials + bias -> out (full chip, split-partial) ----------------
__global__ void k_red(const float* __restrict__ bias, const float* __restrict__ parts,
                      float* __restrict__ out)
{
    int t = blockIdx.x * 256 + threadIdx.x;   // 0..65535
    int o = t >> 2;                            // float4 slot 0..16383
    int pg = t & 3;

    float4 bv = make_float4(0.f, 0.f, 0.f, 0.f);
    if (pg == 0) {
        int i4 = (o * 4) & (HH - 1);
        bv = *(const float4*)(bias + i4);
    }

    cudaGridDependencySynchronize();   // partials ready

    float4 v = make_float4(0.f, 0.f, 0.f, 0.f);
#pragma unroll
    for (int p = 0; p < 4; p++) {
        float4 x = *(const float4*)(parts + (size_t)(pg * 4 + p) * BB * HH + (size_t)o * 4);
        v.x += x.x; v.y += x.y; v.z += x.z; v.w += x.w;
    }
#pragma unroll
    for (int off = 1; off <= 2; off <<= 1) {
        v.x += __shfl_xor_sync(0xffffffffu, v.x, off);
        v.y += __shfl_xor_sync(0xffffffffu, v.y, off);
        v.z += __shfl_xor_sync(0xffffffffu, v.z, off);
        v.w += __shfl_xor_sync(0xffffffffu, v.w, off);
    }
    if (pg == 0) {
        v.x += bv.x; v.y += bv.y; v.z += bv.z; v.w += bv.w;
        *(float4*)(out + (size_t)o * 4) = v;
    }
}

// ---------------- PDL launch helper ----------------
static void launch_pdl(const void* func, dim3 grid, dim3 block, void** args)
{
    cudaLaunchConfig_t cfg = {};
    cfg.gridDim = grid;
    cfg.blockDim = block;
    cfg.dynamicSmemBytes = 0;
    cfg.stream = 0;
    cudaLaunchAttribute attr[1];
    attr[0].id = cudaLaunchAttributeProgrammaticStreamSerialization;
    attr[0].val.programmaticStreamSerializationAllowed = 1;
    cfg.attrs = attr;
    cfg.numAttrs = 1;
    cudaLaunchKernelExC(&cfg, func, args);
}

// ---------------- launch ----------------
extern "C" void kernel_launch(void* const* d_in, const int* in_sizes, int n_in,
                              void* d_out, int out_size)
{
    const float* ctx   = (const float*)d_in[0];
    const float* key   = (const float*)d_in[1];
    const float* mask  = (const float*)d_in[2];
    const float* fc1_w = (const float*)d_in[3];
    const float* fc1_b = (const float*)d_in[4];
    const float* bn_g  = (const float*)d_in[5];
    const float* bn_b  = (const float*)d_in[6];
    const float* fc2_w = (const float*)d_in[7];
    const float* fc2_b = (const float*)d_in[8];

    float* out_x  = (float*)d_out;                 // (B, H)
    float* out_at = (float*)d_out + BB * HH;       // (B, S)

    float *p_x1p, *p_x3p, *p_attn, *p_x2;
    cudaGetSymbolAddress((void**)&p_x1p, g_x1p);
    cudaGetSymbolAddress((void**)&p_x3p, g_x3p);
    cudaGetSymbolAddress((void**)&p_attn, g_attn);
    cudaGetSymbolAddress((void**)&p_x2,  g_x2);

    // 1) fused scores + online softmax weighted sum (single pass over ctx)
    k_attn_partial<<<NBLK1, 256>>>(ctx, key, mask, out_at);

    // 2) merge chunk partials -> g_attn, normalize At
    {
        void* args[] = { &out_at };
        launch_pdl((const void*)k_combine, dim3(5, BB), dim3(256), args);
    }
    // 3) fc1: [attn | key] @ fc1_w^T   (K=2048, ksplit=16, kchunk=128)
    {
        int ws = 2 * HH, kc = 128;
        void* args[] = { &p_attn, (void*)&key, (void*)&fc1_w, &ws, &kc, &p_x1p };
        launch_pdl((const void*)k_gemm, dim3(8, NSPLIT), dim3(256), args);
    }
    // 4) fused reduce + bias + batchnorm + tanh -> g_x2
    {
        void* args[] = { (void*)&fc1_b, (void*)&bn_g, (void*)&bn_b };
        launch_pdl((const void*)k_red_bn, dim3(128), dim3(256), args);
    }
    // 5) fc2 (K=1024, ksplit=16, kchunk=64)
    {
        int ws = HH, kc = 64;
        void* args[] = { &p_x2, &p_x2, (void*)&fc2_w, &ws, &kc, &p_x3p };
        launch_pdl((const void*)k_gemm, dim3(8, NSPLIT), dim3(256), args);
    }
    // 6) reduce + bias -> out
    {
        void* args[] = { (void*)&fc2_b, &p_x3p, &out_x };
        launch_pdl((const void*)k_red, dim3(256), dim3(256), args);
    }
}